// round 4
// baseline (speedup 1.0000x reference)
#include <cuda_runtime.h>
#include <math.h>

#define BATCH 128
#define HID   512
#define ATT   128
#define TT    256
#define CC    256
#define NEG_SLOPE 0.01f
#define NBLK  128
#define NTHR  512

typedef unsigned long long u64;

// -------------------- device-global scratch (no allocs allowed) ----------------
__device__ float g_h1[BATCH * HID];
__device__ float g_c1[BATCH * HID];
__device__ float g_h2[BATCH * HID];
__device__ float g_c2[BATCH * HID];
__device__ float g_h3[BATCH * HID];
__device__ float g_c3[BATCH * HID];
__device__ float g_ctx[BATCH * ATT];
__device__ float g_part[8 * BATCH * 2048];    // split-K partials, gate GEMMs
__device__ float g_mpart[16 * BATCH * HID];   // split-K partials, mlp GEMM
__device__ unsigned g_flags[NBLK];            // grid barrier epochs (monotonic)

// -------------------- shared memory union --------------------------------------
struct GemmSmem { float As[32][132]; float Ws[32][132]; };
struct AttSmem  { float hs[NTHR]; float pr[NTHR]; float qs[ATT]; float at[TT]; float red[16]; };
struct ProjSmem { float ms[HID]; float pr[NTHR]; float red[16]; };
union SmemAll { GemmSmem g; AttSmem a; ProjSmem p; };

// -------------------- packed f32x2 FMA ------------------------------------------
__device__ __forceinline__ u64 pack2(float x, float y) {
    u64 r; asm("mov.b64 %0, {%1, %2};" : "=l"(r) : "f"(x), "f"(y)); return r;
}
__device__ __forceinline__ u64 splat2(float x) {
    u64 r; asm("mov.b64 %0, {%1, %1};" : "=l"(r) : "f"(x)); return r;
}
__device__ __forceinline__ void ffma2(u64& d, u64 a, u64 b) {
    asm("fma.rn.f32x2 %0, %1, %2, %3;" : "=l"(d) : "l"(a), "l"(b), "l"(d));
}

// -------------------- grid barrier ----------------------------------------------
__device__ __forceinline__ void st_rel(unsigned* p, unsigned v) {
    asm volatile("st.release.gpu.u32 [%0], %1;" :: "l"(p), "r"(v) : "memory");
}
__device__ __forceinline__ unsigned ld_acq(const unsigned* p) {
    unsigned v;
    asm volatile("ld.acquire.gpu.u32 %0, [%1];" : "=r"(v) : "l"(p) : "memory");
    return v;
}
__device__ __forceinline__ void gbar(unsigned target) {
    __syncthreads();
    if (threadIdx.x == 0) st_rel(&g_flags[blockIdx.x], target);
    if (threadIdx.x < NBLK) {
        while (ld_acq(&g_flags[threadIdx.x]) < target) __nanosleep(32);
    }
    __syncthreads();
}

// -------------------- reductions (512 threads = 16 warps) ------------------------
__device__ __forceinline__ float warpMax(float v) {
    #pragma unroll
    for (int o = 16; o; o >>= 1) v = fmaxf(v, __shfl_xor_sync(0xffffffffu, v, o));
    return v;
}
__device__ __forceinline__ float warpSum(float v) {
    #pragma unroll
    for (int o = 16; o; o >>= 1) v += __shfl_xor_sync(0xffffffffu, v, o);
    return v;
}
__device__ float blockMax(float v, float* red) {
    v = warpMax(v);
    if ((threadIdx.x & 31) == 0) red[threadIdx.x >> 5] = v;
    __syncthreads();
    if (threadIdx.x < 32) {
        float x = (threadIdx.x < 16) ? red[threadIdx.x] : -3.4e38f;
        x = warpMax(x);
        if (threadIdx.x == 0) red[0] = x;
    }
    __syncthreads();
    float r = red[0];
    __syncthreads();
    return r;
}
__device__ float blockSum(float v, float* red) {
    v = warpSum(v);
    if ((threadIdx.x & 31) == 0) red[threadIdx.x >> 5] = v;
    __syncthreads();
    if (threadIdx.x < 32) {
        float x = (threadIdx.x < 16) ? red[threadIdx.x] : 0.f;
        x = warpSum(x);
        if (threadIdx.x == 0) red[0] = x;
    }
    __syncthreads();
    float r = red[0];
    __syncthreads();
    return r;
}

// -------------------- GEMM tile loader (GMEM -> regs, 2 float4 each) -------------
__device__ __forceinline__ void gemm_load(
    float4* areg, float4* wreg, int kb, int N0, int lm, int lkg, int t,
    const float* emb, const int* Yin, int ystride, int s0,
    const float* p1, int l1, int s1,
    const float* p2, int l2,
    const float* W1, int wk1, const float* W2)
{
    #pragma unroll
    for (int i = 0; i < 2; i++) {
        const int gk = kb + lkg + i * 4;
        const float* ap;
        if (gk < s0)      ap = emb + (size_t)Yin[lm * ystride + t] * HID + gk;
        else if (gk < s1) ap = p1 + (size_t)lm * l1 + (gk - s0);
        else              ap = p2 + (size_t)lm * l2 + (gk - s1);
        areg[i] = *reinterpret_cast<const float4*>(ap);

        const float* wp = (gk < wk1)
            ? W1 + (size_t)(N0 + lm) * wk1 + gk
            : W2 + (size_t)(N0 + lm) * HID + (gk - wk1);
        wreg[i] = *reinterpret_cast<const float4*>(wp);
    }
}

// -------------------- GEMM phase --------------------------------------------------
// part[ks][BATCH][partN] = A(128 x K) @ W(128 x K)^T, tile 128x128, split-K.
// A virtual row m: k<s0: emb[Yin[m]] ; k<s1: p1 ; else p2.
// W virtual row n: k<wk1: W1 (ld wk1) ; else W2 (ld HID).
__device__ void gemm_phase(SmemAll& SS, int t,
    float* part, int partN, int ntN, int n32, int ksplit,
    const float* emb, const int* Yin, int ystride, int s0,
    const float* p1, int l1, int s1,
    const float* p2, int l2,
    const float* W1, int wk1, const float* W2)
{
    const int bid = blockIdx.x;
    if (bid >= ntN * ksplit) return;
    GemmSmem& S = SS.g;
    const int tid = threadIdx.x;
    const int nt = bid / ksplit;
    const int ks = bid % ksplit;
    const int N0 = nt * 128;
    const int q = n32 / ksplit, r = n32 % ksplit;
    const int cnt = q + (ks < r ? 1 : 0);
    const int t0 = ks * q + (ks < r ? ks : r);

    const int lm  = tid & 127;          // load row (A: m, W: n-local)
    const int lkg = (tid >> 7) << 3;    // load k offset (8 per thread)
    const int tx = tid & 15;            // N: 8 cols (4 + 4 at +64)
    const int ty = tid >> 4;            // M: 4 rows (0..31 -> rows ty*4..)

    u64 acc[4][4];                      // [m][packed-pair]: pairs (tx*4+0,1)(+2,3)(+64,65)(+66,67)
    #pragma unroll
    for (int m = 0; m < 4; m++)
        #pragma unroll
        for (int j = 0; j < 4; j++) acc[m][j] = 0ull;

    float4 areg[2], wreg[2];
    gemm_load(areg, wreg, t0 * 32, N0, lm, lkg, t,
              emb, Yin, ystride, s0, p1, l1, s1, p2, l2, W1, wk1, W2);

    for (int tt = 0; tt < cnt; tt++) {
        __syncthreads();
        #pragma unroll
        for (int i = 0; i < 2; i++) {
            S.As[lkg + i * 4 + 0][lm] = areg[i].x;
            S.As[lkg + i * 4 + 1][lm] = areg[i].y;
            S.As[lkg + i * 4 + 2][lm] = areg[i].z;
            S.As[lkg + i * 4 + 3][lm] = areg[i].w;
            S.Ws[lkg + i * 4 + 0][lm] = wreg[i].x;
            S.Ws[lkg + i * 4 + 1][lm] = wreg[i].y;
            S.Ws[lkg + i * 4 + 2][lm] = wreg[i].z;
            S.Ws[lkg + i * 4 + 3][lm] = wreg[i].w;
        }
        __syncthreads();

        if (tt + 1 < cnt) {
            gemm_load(areg, wreg, (t0 + tt + 1) * 32, N0, lm, lkg, t,
                      emb, Yin, ystride, s0, p1, l1, s1, p2, l2, W1, wk1, W2);
        }

        #pragma unroll 8
        for (int k = 0; k < 32; k++) {
            const float4 a = *reinterpret_cast<const float4*>(&S.As[k][ty * 4]);
            const ulonglong2 w01 = *reinterpret_cast<const ulonglong2*>(&S.Ws[k][tx * 4]);
            const ulonglong2 w23 = *reinterpret_cast<const ulonglong2*>(&S.Ws[k][tx * 4 + 64]);
            const u64 aa[4] = {splat2(a.x), splat2(a.y), splat2(a.z), splat2(a.w)};
            #pragma unroll
            for (int m = 0; m < 4; m++) {
                ffma2(acc[m][0], aa[m], w01.x);
                ffma2(acc[m][1], aa[m], w01.y);
                ffma2(acc[m][2], aa[m], w23.x);
                ffma2(acc[m][3], aa[m], w23.y);
            }
        }
    }

    // epilogue: write split-K partials (16B stores)
    #pragma unroll
    for (int m = 0; m < 4; m++) {
        const int row = ty * 4 + m;
        float* op = part + ((size_t)(ks * BATCH + row)) * partN + N0;
        ulonglong2 v0; v0.x = acc[m][0]; v0.y = acc[m][1];
        ulonglong2 v1; v1.x = acc[m][2]; v1.y = acc[m][3];
        *reinterpret_cast<ulonglong2*>(op + tx * 4)      = v0;
        *reinterpret_cast<ulonglong2*>(op + 64 + tx * 4) = v1;
    }
}

// -------------------- LSTM pointwise update (block = batch row) -------------------
__device__ void update_phase(float* h, float* c, const float* bih, const float* bhh)
{
    const int b = blockIdx.x;
    const int j = threadIdx.x;   // 0..511 == HID
    float gi = bih[j] + bhh[j];
    float gf = bih[j + 512] + bhh[j + 512];
    float gg = bih[j + 1024] + bhh[j + 1024];
    float go = bih[j + 1536] + bhh[j + 1536];
    #pragma unroll
    for (int ks = 0; ks < 8; ks++) {
        const float* pk = g_part + (size_t)(ks * BATCH + b) * 2048;
        gi += pk[j];
        gf += pk[j + 512];
        gg += pk[j + 1024];
        go += pk[j + 1536];
    }
    const float ig = 1.f / (1.f + expf(-gi));
    const float fg = 1.f / (1.f + expf(-gf));
    const float og = 1.f / (1.f + expf(-go));
    const float gv = tanhf(gg);
    const int idx = b * HID + j;
    const float cn = fg * c[idx] + ig * gv;
    c[idx] = cn;
    h[idx] = og * tanhf(cn);
}

// -------------------- fused attention (block = batch row, 512 thr) ----------------
__device__ void attend_phase(SmemAll& SS, const float* key, const float* value,
                             const int* flens, const float* Wq, const float* bq)
{
    AttSmem& A = SS.a;
    const int b = blockIdx.x;
    const int tid = threadIdx.x;

    A.hs[tid] = g_h3[b * HID + tid];
    __syncthreads();

    // q = h3 @ Wq^T + bq : 4 threads per output a, 128 k each
    {
        const int a = tid & 127;
        const int p = tid >> 7;
        const float* wr = Wq + (size_t)a * HID + p * 128;
        const float* hr = A.hs + p * 128;
        float s = 0.f;
        #pragma unroll 8
        for (int k = 0; k < 128; k += 4) {
            const float4 w = *reinterpret_cast<const float4*>(wr + k);
            s += w.x * hr[k] + w.y * hr[k + 1] + w.z * hr[k + 2] + w.w * hr[k + 3];
        }
        A.pr[tid] = s;
    }
    __syncthreads();
    if (tid < ATT)
        A.qs[tid] = A.pr[tid] + A.pr[tid + 128] + A.pr[tid + 256] + A.pr[tid + 384] + bq[tid];
    __syncthreads();

    // energy: 2 threads per position t (64 a each)
    {
        const int tp = tid & 255;
        const int hf = tid >> 8;
        const float* kp = key + (size_t)b * ATT * TT + tp;
        float e = 0.f;
        #pragma unroll 8
        for (int a = 0; a < 64; a++) e += A.qs[hf * 64 + a] * kp[(size_t)(hf * 64 + a) * TT];
        A.pr[tid] = e;
    }
    __syncthreads();

    const int flen = flens[b] >> 3;
    const float ev = (tid < 256) ? (A.pr[tid] + A.pr[tid + 256]) : -3.4e38f;
    const float mx = blockMax(ev, A.red);
    const float w = (tid < 256 && tid < flen) ? expf(ev - mx) : 0.f;
    const float sm = blockSum(w, A.red);
    if (tid < 256) A.at[tid] = w / sm;
    __syncthreads();

    // ctx = attn @ value : 4 threads per output v, 64 t each
    {
        const int v = tid & 127;
        const int p = tid >> 7;
        const float* vp = value + (size_t)b * TT * ATT + (size_t)(p * 64) * ATT + v;
        float cs = 0.f;
        #pragma unroll 8
        for (int t2 = 0; t2 < 64; t2++) cs += A.at[p * 64 + t2] * vp[(size_t)t2 * ATT];
        A.pr[tid] = cs;
    }
    __syncthreads();
    if (tid < ATT)
        g_ctx[b * ATT + tid] = A.pr[tid] + A.pr[tid + 128] + A.pr[tid + 256] + A.pr[tid + 384];
}

// -------------------- mlp-combine + projection + log-softmax ----------------------
__device__ void proj_phase(SmemAll& SS, const float* emb, const float* bproj,
                           const float* bmlp, float* out, int t, int ml)
{
    ProjSmem& P = SS.p;
    const int b = blockIdx.x;
    const int tid = threadIdx.x;

    // combine mlp split-K partials + bias + LeakyReLU (fixed order => deterministic)
    {
        float s = bmlp[tid];
        #pragma unroll
        for (int ks = 0; ks < 16; ks++)
            s += g_mpart[((size_t)(ks * BATCH) + b) * HID + tid];
        P.ms[tid] = (s >= 0.f) ? s : NEG_SLOPE * s;
    }
    __syncthreads();

    // logits: 2 threads per class c (256 k each)
    {
        const int c = tid & 255;
        const int hf = tid >> 8;
        const float* er = emb + (size_t)c * HID + hf * 256;
        const float* mr = P.ms + hf * 256;
        float s = 0.f;
        #pragma unroll 8
        for (int k = 0; k < 256; k += 4) {
            const float4 w = *reinterpret_cast<const float4*>(er + k);
            s += w.x * mr[k] + w.y * mr[k + 1] + w.z * mr[k + 2] + w.w * mr[k + 3];
        }
        P.pr[tid] = s;
    }
    __syncthreads();

    const float lv = (tid < 256) ? (P.pr[tid] + P.pr[tid + 256] + bproj[tid]) : -3.4e38f;
    const float mx = blockMax(lv, P.red);
    const float ex = (tid < 256) ? expf(lv - mx) : 0.f;
    const float sm = blockSum(ex, P.red);
    if (tid < 256)
        out[((size_t)b * ml + t) * CC + tid] = lv - mx - logf(sm);
    __syncthreads();   // protect smem before next phase reuses the union
}

// -------------------- persistent megakernel ----------------------------------------
__global__ __launch_bounds__(NTHR, 1) void mega_kernel(
    const float* key, const float* value, const int* Yin, const int* flens,
    const float* emb, const float* Wq, const float* bq,
    const float* Wih1, const float* Whh1, const float* bih1, const float* bhh1,
    const float* Wih2, const float* Whh2, const float* bih2, const float* bhh2,
    const float* Wih3, const float* Whh3, const float* bih3, const float* bhh3,
    const float* Wmlp, const float* bmlp, const float* bproj,
    const float* h00, const float* h01, const float* h02,
    const float* c00, const float* c01, const float* c02,
    float* out, int ml, int ystride)
{
    __shared__ SmemAll S;
    const unsigned base = g_flags[blockIdx.x];   // monotonic epochs across replays
    unsigned bn = 0;

    // init state (broadcast initial h/c); 128*512 threads == BATCH*HID
    {
        const int idx = blockIdx.x * NTHR + threadIdx.x;
        const int j = idx & 511;
        g_h1[idx] = h00[j]; g_h2[idx] = h01[j]; g_h3[idx] = h02[j];
        g_c1[idx] = c00[j]; g_c2[idx] = c01[j]; g_c3[idx] = c02[j];
    }
    gbar(base + ++bn);
    attend_phase(S, key, value, flens, Wq, bq);
    gbar(base + ++bn);

    for (int t = 0; t < ml; t++) {
        // LSTM1: A = [emb[y_t] | ctx | h1], W = [Wih1 | Whh1], K=1152
        gemm_phase(S, t, g_part, 2048, 16, 36, 8,
                   emb, Yin, ystride, 512,
                   g_ctx, ATT, 640, g_h1, HID,
                   Wih1, 640, Whh1);
        gbar(base + ++bn);
        update_phase(g_h1, g_c1, bih1, bhh1);
        gbar(base + ++bn);

        // LSTM2: A = [h1 | h2], K=1024
        gemm_phase(S, t, g_part, 2048, 16, 32, 8,
                   nullptr, nullptr, 0, 0,
                   g_h1, HID, 512, g_h2, HID,
                   Wih2, 512, Whh2);
        gbar(base + ++bn);
        update_phase(g_h2, g_c2, bih2, bhh2);
        gbar(base + ++bn);

        // LSTM3: A = [h2 | h3], K=1024
        gemm_phase(S, t, g_part, 2048, 16, 32, 8,
                   nullptr, nullptr, 0, 0,
                   g_h2, HID, 512, g_h3, HID,
                   Wih3, 512, Whh3);
        gbar(base + ++bn);
        update_phase(g_h3, g_c3, bih3, bhh3);
        gbar(base + ++bn);

        // attention from new h3
        attend_phase(S, key, value, flens, Wq, bq);
        gbar(base + ++bn);

        // mlp: A = [h3 | ctx], W = Wmlp, K=640, N=512, split-K 16
        gemm_phase(S, t, g_mpart, HID, 4, 20, 16,
                   nullptr, nullptr, 0, 0,
                   g_h3, HID, 512, g_ctx, ATT,
                   Wmlp, 640, nullptr);
        gbar(base + ++bn);

        // combine + LeakyReLU + tied projection + log-softmax
        proj_phase(S, emb, bproj, bmlp, out, t, ml);
        // no grid barrier needed: proj reads g_mpart (barriered), writes out only
    }
}

// -------------------- launch ----------------------------------------------------------
extern "C" void kernel_launch(void* const* d_in, const int* in_sizes, int n_in,
                              void* d_out, int out_size)
{
    const float* key        = (const float*)d_in[0];
    const float* value      = (const float*)d_in[1];
    const int*   Yinput     = (const int*)d_in[2];
    const int*   frame_lens = (const int*)d_in[3];
    // d_in[4] = max_len scalar; derived from out_size instead
    const float* emb   = (const float*)d_in[5];
    const float* Wq    = (const float*)d_in[6];
    const float* bq    = (const float*)d_in[7];
    const float* Wih1  = (const float*)d_in[8];
    const float* Whh1  = (const float*)d_in[9];
    const float* bih1  = (const float*)d_in[10];
    const float* bhh1  = (const float*)d_in[11];
    const float* Wih2  = (const float*)d_in[12];
    const float* Whh2  = (const float*)d_in[13];
    const float* bih2  = (const float*)d_in[14];
    const float* bhh2  = (const float*)d_in[15];
    const float* Wih3  = (const float*)d_in[16];
    const float* Whh3  = (const float*)d_in[17];
    const float* bih3  = (const float*)d_in[18];
    const float* bhh3  = (const float*)d_in[19];
    const float* Wmlp  = (const float*)d_in[20];
    const float* bmlp  = (const float*)d_in[21];
    const float* bproj = (const float*)d_in[22];
    const float* h00 = (const float*)d_in[23];
    const float* h01 = (const float*)d_in[24];
    const float* h02 = (const float*)d_in[25];
    const float* c00 = (const float*)d_in[26];
    const float* c01 = (const float*)d_in[27];
    const float* c02 = (const float*)d_in[28];

    float* out = (float*)d_out;
    const int ml = out_size / (BATCH * CC);     // 300
    const int ystride = in_sizes[2] / BATCH;    // MAXLEN = 300

    mega_kernel<<<NBLK, NTHR>>>(
        key, value, Yinput, frame_lens,
        emb, Wq, bq,
        Wih1, Whh1, bih1, bhh1,
        Wih2, Whh2, bih2, bhh2,
        Wih3, Whh3, bih3, bhh3,
        Wmlp, bmlp, bproj,
        h00, h01, h02, c00, c01, c02,
        out, ml, ystride);
}